// round 1
// baseline (speedup 1.0000x reference)
#include <cuda_runtime.h>
#include <cstdint>

// Problem constants
#define BATCH    16384
#define N_OBJ    16
#define DIM_IN   256
#define N_COLS   64        // N_ATTR * N_PARAM * D_ATTR = 4*2*8
#define BM       128       // rows per block
#define NWARPS   8         // 8 warps * 16 rows = 128 rows
#define WSTRIDE  260       // padded d-stride for W smem (bank-conflict-free)

// Shared: W tf32 [64][260] + bias[64]
#define SMEM_W_WORDS (N_COLS * WSTRIDE)          // 16640
#define SMEM_BYTES   ((SMEM_W_WORDS + N_COLS) * 4)

__device__ __forceinline__ uint32_t f2tf32(float f) {
    uint32_t r;
    asm("cvt.rna.tf32.f32 %0, %1;" : "=r"(r) : "f"(f));
    return r;
}

__global__ void __launch_bounds__(256, 2)
objdec_kernel(const float* __restrict__ x,
              const float* __restrict__ W,
              const float* __restrict__ bias,
              float* __restrict__ out)
{
    extern __shared__ uint32_t sh[];
    uint32_t* Wsm = sh;                         // [n*260 + d], tf32 bits
    float*    bsm = (float*)(sh + SMEM_W_WORDS);

    const int tid  = threadIdx.x;
    const int o    = blockIdx.y;                // object index
    const int rbase = blockIdx.x * BM;          // first row of this tile

    // ---- Stage W[o] into smem, remapped to [n][d], converted to tf32 ----
    // global: W[o,a,p,d,k] ; n = a*16 + p*8 + k
    {
        const float* Wg = W + (size_t)o * (N_COLS * DIM_IN);
        for (int idx = tid; idx < N_COLS * DIM_IN; idx += 256) {
            int d = idx >> 6;          // 0..255
            int n = idx & 63;          // 0..63
            int a = n >> 4;
            int p = (n >> 3) & 1;
            int k = n & 7;
            float v = Wg[a * 4096 + p * 2048 + d * 8 + k];
            Wsm[n * WSTRIDE + d] = f2tf32(v);
        }
        if (tid < N_COLS) bsm[tid] = bias[o * N_COLS + tid];
    }
    __syncthreads();

    // ---- Warp tiling: warp w covers rows [rbase + w*16, +16), all 64 cols ----
    const int warp = tid >> 5;
    const int lane = tid & 31;
    const int g = lane >> 2;     // 0..7  (row group / n within n-tile)
    const int c = lane & 3;      // 0..3  (k within k-step half)

    const int rowA0 = rbase + warp * 16 + g;
    const float* A0 = x + (size_t)rowA0 * (N_OBJ * DIM_IN) + o * DIM_IN;
    const float* A1 = A0 + 8 * (N_OBJ * DIM_IN);

    float acc[8][4];
    #pragma unroll
    for (int j = 0; j < 8; ++j)
        #pragma unroll
        for (int q = 0; q < 4; ++q) acc[j][q] = 0.0f;

    // ---- Main loop over K=256 in steps of 8 ----
    #pragma unroll 4
    for (int kb = 0; kb < DIM_IN; kb += 8) {
        uint32_t a0 = f2tf32(A0[kb + c]);
        uint32_t a1 = f2tf32(A1[kb + c]);
        uint32_t a2 = f2tf32(A0[kb + 4 + c]);
        uint32_t a3 = f2tf32(A1[kb + 4 + c]);

        const uint32_t* Wp = Wsm + kb + c;
        #pragma unroll
        for (int j = 0; j < 8; ++j) {
            uint32_t b0 = Wp[(j * 8 + g) * WSTRIDE];
            uint32_t b1 = Wp[(j * 8 + g) * WSTRIDE + 4];
            asm volatile(
                "mma.sync.aligned.m16n8k8.row.col.f32.tf32.tf32.f32 "
                "{%0,%1,%2,%3}, {%4,%5,%6,%7}, {%8,%9}, {%0,%1,%2,%3};\n"
                : "+f"(acc[j][0]), "+f"(acc[j][1]), "+f"(acc[j][2]), "+f"(acc[j][3])
                : "r"(a0), "r"(a1), "r"(a2), "r"(a3), "r"(b0), "r"(b1));
        }
    }

    // ---- Epilogue: bias + store (float2 per row per n-tile) ----
    const int row0 = rbase + warp * 16 + g;      // == rowA0
    const int row1 = row0 + 8;
    #pragma unroll
    for (int j = 0; j < 8; ++j) {
        int col = j * 8 + 2 * c;
        float bv0 = bsm[col];
        float bv1 = bsm[col + 1];
        float2 v0 = make_float2(acc[j][0] + bv0, acc[j][1] + bv1);
        float2 v1 = make_float2(acc[j][2] + bv0, acc[j][3] + bv1);
        float* p0 = out + (size_t)row0 * (N_OBJ * N_COLS) + o * N_COLS + col;
        float* p1 = out + (size_t)row1 * (N_OBJ * N_COLS) + o * N_COLS + col;
        *reinterpret_cast<float2*>(p0) = v0;
        *reinterpret_cast<float2*>(p1) = v1;
    }
}

extern "C" void kernel_launch(void* const* d_in, const int* in_sizes, int n_in,
                              void* d_out, int out_size)
{
    (void)in_sizes; (void)n_in; (void)out_size;
    const float* x = (const float*)d_in[0];
    const float* W = (const float*)d_in[1];
    const float* b = (const float*)d_in[2];
    float* out = (float*)d_out;

    // Idempotent; safe under graph capture (not a stream op).
    cudaFuncSetAttribute(objdec_kernel,
                         cudaFuncAttributeMaxDynamicSharedMemorySize, SMEM_BYTES);

    dim3 grid(BATCH / BM, N_OBJ);
    objdec_kernel<<<grid, 256, SMEM_BYTES>>>(x, W, b, out);
}

// round 2
// speedup vs baseline: 1.1619x; 1.1619x over previous
#include <cuda_runtime.h>
#include <cstdint>

// Problem constants
#define BATCH    16384
#define N_OBJ    16
#define DIM_IN   256
#define N_COLS   64        // N_ATTR * N_PARAM * D_ATTR = 4*2*8
#define BM       128       // rows per block
#define ROWSTRIDE (N_OBJ * DIM_IN)   // 4096 floats between batch rows
#define OUTSTRIDE (N_OBJ * N_COLS)   // 1024 floats between batch rows of out

#define WSTRIDE  260       // W smem d-stride (260%32==4 -> conflict-free frags)
#define KC       64        // k-chunk (floats) staged per iteration
#define NCHUNK   (DIM_IN / KC)       // 4
#define ASTRIDE  68        // A smem k-stride (68%32==4 -> conflict-free frags)

#define SMEM_W_WORDS   (N_COLS * WSTRIDE)        // 16640
#define SMEM_BIAS_OFF  SMEM_W_WORDS
#define SMEM_A_OFF     (SMEM_W_WORDS + N_COLS)   // 16704
#define SMEM_A_WORDS   (BM * ASTRIDE)            // 8704
#define SMEM_BYTES     ((SMEM_A_OFF + SMEM_A_WORDS) * 4)   // 101,632 B

__device__ __forceinline__ uint32_t f2tf32(float f) {
    uint32_t r;
    asm("cvt.rna.tf32.f32 %0, %1;" : "=r"(r) : "f"(f));
    return r;
}

__global__ void __launch_bounds__(256, 2)
objdec_kernel(const float* __restrict__ x,
              const float* __restrict__ W,
              const float* __restrict__ bias,
              float* __restrict__ out)
{
    extern __shared__ uint32_t sh[];
    uint32_t* Wsm = sh;                          // [n][d] tf32 bits, stride 260
    float*    bsm = (float*)(sh + SMEM_BIAS_OFF);
    uint32_t* Asm = sh + SMEM_A_OFF;             // [row][k] tf32 bits, stride 68

    const int tid   = threadIdx.x;
    const int o     = blockIdx.y;
    const int rbase = blockIdx.x * BM;

    // ---- Stage W[o] -> smem [n][d] tf32. Coalesced global reads. ----
    {
        const float* Wg = W + (size_t)o * (N_COLS * DIM_IN);
        #pragma unroll 4
        for (int m = tid; m < N_COLS * DIM_IN; m += 256) {
            // global linear m = ((a*2+p)*256 + d)*8 + k
            int k = m & 7;
            int d = (m >> 3) & 255;
            int a = m >> 12;
            int p = (m >> 11) & 1;
            int n = a * 16 + p * 8 + k;
            Wsm[n * WSTRIDE + d] = f2tf32(Wg[m]);
        }
        if (tid < N_COLS) bsm[tid] = bias[o * N_COLS + tid];
    }

    // ---- A staging addressing: thread -> (row = p*16 + tid/16, kq = tid%16) ----
    const int arow = tid >> 4;         // 0..15
    const int akq  = tid & 15;         // 0..15 (float4 index within 64-float chunk)
    const float* xg = x + (size_t)rbase * ROWSTRIDE + o * DIM_IN;

    float4 pref[8];
    #pragma unroll
    for (int p = 0; p < 8; ++p) {
        pref[p] = *(const float4*)(xg + (size_t)(p * 16 + arow) * ROWSTRIDE + akq * 4);
    }
    #pragma unroll
    for (int p = 0; p < 8; ++p) {
        uint32_t* dst = Asm + (p * 16 + arow) * ASTRIDE + akq * 4;
        dst[0] = f2tf32(pref[p].x);
        dst[1] = f2tf32(pref[p].y);
        dst[2] = f2tf32(pref[p].z);
        dst[3] = f2tf32(pref[p].w);
    }
    __syncthreads();

    // ---- Warp tiling: warp = (mwarp 0..3) x (nwarp 0..1); 32 rows x 32 cols ----
    const int warp  = tid >> 5;
    const int lane  = tid & 31;
    const int mwarp = warp & 3;
    const int nwarp = warp >> 2;
    const int g = lane >> 2;           // 0..7
    const int c = lane & 3;            // 0..3

    float acc[2][4][4];
    #pragma unroll
    for (int mi = 0; mi < 2; ++mi)
        #pragma unroll
        for (int j = 0; j < 4; ++j)
            #pragma unroll
            for (int q = 0; q < 4; ++q) acc[mi][j][q] = 0.0f;

    const uint32_t* Arow0 = Asm + (mwarp * 32 + g) * ASTRIDE + c;          // mi=0
    const uint32_t* Arow1 = Asm + (mwarp * 32 + 16 + g) * ASTRIDE + c;     // mi=1
    const uint32_t* Wp    = Wsm + (nwarp * 32 + g) * WSTRIDE + c;

    for (int ck = 0; ck < NCHUNK; ++ck) {
        // prefetch next chunk while computing this one
        if (ck < NCHUNK - 1) {
            #pragma unroll
            for (int p = 0; p < 8; ++p) {
                pref[p] = *(const float4*)(xg + (size_t)(p * 16 + arow) * ROWSTRIDE
                                           + (ck + 1) * KC + akq * 4);
            }
        }

        const int kg0 = ck * KC;       // global k of this chunk
        #pragma unroll
        for (int kb = 0; kb < KC; kb += 8) {
            // A fragments (conflict-free LDS, 8 x LDS.32 per warp)
            uint32_t a0[4], a1[4];
            a0[0] = Arow0[kb];                 a0[1] = Arow0[8 * ASTRIDE + kb];
            a0[2] = Arow0[kb + 4];             a0[3] = Arow0[8 * ASTRIDE + kb + 4];
            a1[0] = Arow1[kb];                 a1[1] = Arow1[8 * ASTRIDE + kb];
            a1[2] = Arow1[kb + 4];             a1[3] = Arow1[8 * ASTRIDE + kb + 4];

            // B fragments + MMAs
            #pragma unroll
            for (int j = 0; j < 4; ++j) {
                uint32_t b0 = Wp[j * 8 * WSTRIDE + kg0 + kb];
                uint32_t b1 = Wp[j * 8 * WSTRIDE + kg0 + kb + 4];
                asm volatile(
                    "mma.sync.aligned.m16n8k8.row.col.f32.tf32.tf32.f32 "
                    "{%0,%1,%2,%3}, {%4,%5,%6,%7}, {%8,%9}, {%0,%1,%2,%3};\n"
                    : "+f"(acc[0][j][0]), "+f"(acc[0][j][1]),
                      "+f"(acc[0][j][2]), "+f"(acc[0][j][3])
                    : "r"(a0[0]), "r"(a0[1]), "r"(a0[2]), "r"(a0[3]),
                      "r"(b0), "r"(b1));
                asm volatile(
                    "mma.sync.aligned.m16n8k8.row.col.f32.tf32.tf32.f32 "
                    "{%0,%1,%2,%3}, {%4,%5,%6,%7}, {%8,%9}, {%0,%1,%2,%3};\n"
                    : "+f"(acc[1][j][0]), "+f"(acc[1][j][1]),
                      "+f"(acc[1][j][2]), "+f"(acc[1][j][3])
                    : "r"(a1[0]), "r"(a1[1]), "r"(a1[2]), "r"(a1[3]),
                      "r"(b0), "r"(b1));
            }
        }

        __syncthreads();   // everyone done reading Asm for this chunk
        if (ck < NCHUNK - 1) {
            #pragma unroll
            for (int p = 0; p < 8; ++p) {
                uint32_t* dst = Asm + (p * 16 + arow) * ASTRIDE + akq * 4;
                dst[0] = f2tf32(pref[p].x);
                dst[1] = f2tf32(pref[p].y);
                dst[2] = f2tf32(pref[p].z);
                dst[3] = f2tf32(pref[p].w);
            }
            __syncthreads();
        }
    }

    // ---- Epilogue: bias + float2 stores ----
    #pragma unroll
    for (int mi = 0; mi < 2; ++mi) {
        const int row0 = rbase + mwarp * 32 + mi * 16 + g;
        const int row1 = row0 + 8;
        #pragma unroll
        for (int j = 0; j < 4; ++j) {
            const int col = nwarp * 32 + j * 8 + 2 * c;
            float bv0 = bsm[col];
            float bv1 = bsm[col + 1];
            float2 v0 = make_float2(acc[mi][j][0] + bv0, acc[mi][j][1] + bv1);
            float2 v1 = make_float2(acc[mi][j][2] + bv0, acc[mi][j][3] + bv1);
            float* p0 = out + (size_t)row0 * OUTSTRIDE + o * N_COLS + col;
            float* p1 = out + (size_t)row1 * OUTSTRIDE + o * N_COLS + col;
            *reinterpret_cast<float2*>(p0) = v0;
            *reinterpret_cast<float2*>(p1) = v1;
        }
    }
}

extern "C" void kernel_launch(void* const* d_in, const int* in_sizes, int n_in,
                              void* d_out, int out_size)
{
    (void)in_sizes; (void)n_in; (void)out_size;
    const float* x = (const float*)d_in[0];
    const float* W = (const float*)d_in[1];
    const float* b = (const float*)d_in[2];
    float* out = (float*)d_out;

    cudaFuncSetAttribute(objdec_kernel,
                         cudaFuncAttributeMaxDynamicSharedMemorySize, SMEM_BYTES);

    dim3 grid(BATCH / BM, N_OBJ);
    objdec_kernel<<<grid, 256, SMEM_BYTES>>>(x, W, b, out);
}

// round 3
// speedup vs baseline: 1.6959x; 1.4595x over previous
#include <cuda_runtime.h>
#include <cstdint>

#define BATCH    16384
#define N_OBJ    16
#define DIM_IN   256
#define N_COLS   64
#define BM       128
#define ROWSTRIDE (N_OBJ * DIM_IN)   // 4096
#define OUTSTRIDE (N_OBJ * N_COLS)   // 1024

#define WSTRIDE  260                 // W smem d-stride
#define KC       32                  // k per pipeline chunk
#define NCHUNK   (DIM_IN / KC)       // 8
#define ASTRIDE  36                  // A smem k-stride (bank = 4g+c, injective)
#define ABUFWORDS (BM * ASTRIDE)     // 4608 words per stage

#define SMEM_W_WORDS   (N_COLS * WSTRIDE)            // 16640
#define SMEM_BIAS_OFF  SMEM_W_WORDS
#define SMEM_A_OFF     (SMEM_W_WORDS + N_COLS)       // 16704
#define SMEM_WORDS     (SMEM_A_OFF + 2 * ABUFWORDS)  // 25920
#define SMEM_BYTES     (SMEM_WORDS * 4)              // 103680

__device__ __forceinline__ uint32_t f2tf32(float f) {
    uint32_t r;
    asm("cvt.rna.tf32.f32 %0, %1;" : "=r"(r) : "f"(f));
    return r;
}
__device__ __forceinline__ void cp16(uint32_t dst, const float* src) {
    asm volatile("cp.async.cg.shared.global [%0], [%1], 16;\n"
                 :: "r"(dst), "l"(src));
}

__global__ void __launch_bounds__(256, 2)
objdec_kernel(const float* __restrict__ x,
              const float* __restrict__ W,
              const float* __restrict__ bias,
              float* __restrict__ out)
{
    extern __shared__ uint32_t sh[];
    uint32_t* Wsm = sh;                          // [n][d] tf32, stride 260
    float*    bsm = (float*)(sh + SMEM_BIAS_OFF);
    float*    Afl = (float*)(sh + SMEM_A_OFF);   // 2 stages of raw fp32 x

    const int tid   = threadIdx.x;
    const int o     = blockIdx.y;
    const int rbase = blockIdx.x * BM;
    const float* xg = x + (size_t)rbase * ROWSTRIDE + o * DIM_IN;

    // ---- per-thread cp.async addressing (4 x 16B per chunk) ----
    // linear = tid + q*256 ; row = linear>>3, quad = linear&7
    const float* asrc[4];
    uint32_t adst0[4], adst1[4];
    {
        uint32_t abase = (uint32_t)__cvta_generic_to_shared(Afl);
        #pragma unroll
        for (int q = 0; q < 4; ++q) {
            int lin  = tid + q * 256;
            int row  = lin >> 3;
            int quad = lin & 7;
            asrc[q]  = xg + (size_t)row * ROWSTRIDE + quad * 4;
            adst0[q] = abase + (row * ASTRIDE + quad * 4) * 4;
            adst1[q] = adst0[q] + ABUFWORDS * 4;
        }
    }

    // ---- prefetch chunks 0 and 1 ----
    #pragma unroll
    for (int q = 0; q < 4; ++q) cp16(adst0[q], asrc[q]);
    asm volatile("cp.async.commit_group;\n");
    #pragma unroll
    for (int q = 0; q < 4; ++q) cp16(adst1[q], asrc[q] + KC);
    asm volatile("cp.async.commit_group;\n");

    // ---- stage W[o] -> smem [n][d] tf32 (overlaps with cp.async in flight) ----
    {
        const float* Wg = W + (size_t)o * (N_COLS * DIM_IN);
        #pragma unroll
        for (int i = 0; i < 16; ++i) {
            int idx4 = tid + i * 256;
            int m = idx4 * 4;
            float4 v = *(const float4*)(Wg + m);
            int k = m & 7;
            int d = (m >> 3) & 255;
            int n = (m >> 12) * 16 + ((m >> 11) & 1) * 8 + k;
            uint32_t* dst = Wsm + n * WSTRIDE + d;
            dst[0]           = f2tf32(v.x);
            dst[WSTRIDE]     = f2tf32(v.y);
            dst[2 * WSTRIDE] = f2tf32(v.z);
            dst[3 * WSTRIDE] = f2tf32(v.w);
        }
        if (tid < N_COLS) bsm[tid] = bias[o * N_COLS + tid];
    }

    // ---- warp tiling: 4 mwarps x 2 nwarps; warp = 32 rows x 32 cols ----
    const int warp  = tid >> 5;
    const int lane  = tid & 31;
    const int mwarp = warp & 3;
    const int nwarp = warp >> 2;
    const int g = lane >> 2;
    const int c = lane & 3;

    float acc[2][4][4];
    #pragma unroll
    for (int mi = 0; mi < 2; ++mi)
        #pragma unroll
        for (int j = 0; j < 4; ++j)
            #pragma unroll
            for (int q = 0; q < 4; ++q) acc[mi][j][q] = 0.0f;

    const int aoff = (mwarp * 32 + g) * ASTRIDE + c;   // mi=0 base (fp32 words)
    const uint32_t* Wp = Wsm + (nwarp * 32 + g) * WSTRIDE + c;

    for (int ck = 0; ck < NCHUNK; ++ck) {
        if (ck < NCHUNK - 1) {
            asm volatile("cp.async.wait_group 1;\n" ::: "memory");
        } else {
            asm volatile("cp.async.wait_group 0;\n" ::: "memory");
        }
        __syncthreads();

        const float* Ab = Afl + (ck & 1) * ABUFWORDS + aoff;
        #pragma unroll
        for (int kb = 0; kb < KC; kb += 8) {
            uint32_t a0[4], a1[4];
            a0[0] = f2tf32(Ab[kb]);
            a0[1] = f2tf32(Ab[8 * ASTRIDE + kb]);
            a0[2] = f2tf32(Ab[kb + 4]);
            a0[3] = f2tf32(Ab[8 * ASTRIDE + kb + 4]);
            a1[0] = f2tf32(Ab[16 * ASTRIDE + kb]);
            a1[1] = f2tf32(Ab[24 * ASTRIDE + kb]);
            a1[2] = f2tf32(Ab[16 * ASTRIDE + kb + 4]);
            a1[3] = f2tf32(Ab[24 * ASTRIDE + kb + 4]);

            const int kg = ck * KC + kb;
            #pragma unroll
            for (int j = 0; j < 4; ++j) {
                uint32_t b0 = Wp[j * 8 * WSTRIDE + kg];
                uint32_t b1 = Wp[j * 8 * WSTRIDE + kg + 4];
                asm volatile(
                    "mma.sync.aligned.m16n8k8.row.col.f32.tf32.tf32.f32 "
                    "{%0,%1,%2,%3}, {%4,%5,%6,%7}, {%8,%9}, {%0,%1,%2,%3};\n"
                    : "+f"(acc[0][j][0]), "+f"(acc[0][j][1]),
                      "+f"(acc[0][j][2]), "+f"(acc[0][j][3])
                    : "r"(a0[0]), "r"(a0[1]), "r"(a0[2]), "r"(a0[3]),
                      "r"(b0), "r"(b1));
                asm volatile(
                    "mma.sync.aligned.m16n8k8.row.col.f32.tf32.tf32.f32 "
                    "{%0,%1,%2,%3}, {%4,%5,%6,%7}, {%8,%9}, {%0,%1,%2,%3};\n"
                    : "+f"(acc[1][j][0]), "+f"(acc[1][j][1]),
                      "+f"(acc[1][j][2]), "+f"(acc[1][j][3])
                    : "r"(a1[0]), "r"(a1[1]), "r"(a1[2]), "r"(a1[3]),
                      "r"(b0), "r"(b1));
            }
        }

        __syncthreads();   // all warps done reading this stage
        if (ck + 2 < NCHUNK) {
            const uint32_t* dsts = (ck & 1) ? adst1 : adst0;  // reuse stage ck%2
            const int koff = (ck + 2) * KC;
            #pragma unroll
            for (int q = 0; q < 4; ++q) cp16(dsts[q], asrc[q] + koff);
            asm volatile("cp.async.commit_group;\n");
        }
    }

    // ---- epilogue ----
    #pragma unroll
    for (int mi = 0; mi < 2; ++mi) {
        const int row0 = rbase + mwarp * 32 + mi * 16 + g;
        const int row1 = row0 + 8;
        #pragma unroll
        for (int j = 0; j < 4; ++j) {
            const int col = nwarp * 32 + j * 8 + 2 * c;
            float bv0 = bsm[col];
            float bv1 = bsm[col + 1];
            float2 v0 = make_float2(acc[mi][j][0] + bv0, acc[mi][j][1] + bv1);
            float2 v1 = make_float2(acc[mi][j][2] + bv0, acc[mi][j][3] + bv1);
            float* p0 = out + (size_t)row0 * OUTSTRIDE + o * N_COLS + col;
            float* p1 = out + (size_t)row1 * OUTSTRIDE + o * N_COLS + col;
            *reinterpret_cast<float2*>(p0) = v0;
            *reinterpret_cast<float2*>(p1) = v1;
        }
    }
}

extern "C" void kernel_launch(void* const* d_in, const int* in_sizes, int n_in,
                              void* d_out, int out_size)
{
    (void)in_sizes; (void)n_in; (void)out_size;
    const float* x = (const float*)d_in[0];
    const float* W = (const float*)d_in[1];
    const float* b = (const float*)d_in[2];
    float* out = (float*)d_out;

    cudaFuncSetAttribute(objdec_kernel,
                         cudaFuncAttributeMaxDynamicSharedMemorySize, SMEM_BYTES);

    dim3 grid(BATCH / BM, N_OBJ);
    objdec_kernel<<<grid, 256, SMEM_BYTES>>>(x, W, b, out);
}